// round 11
// baseline (speedup 1.0000x reference)
#include <cuda_runtime.h>

// Gray-Scott residual: y-march version. Each thread computes a z-pair over
// 8 consecutive y outputs, with a 5-deep float2 register ring of center rows
// per channel (y-taps free), z-window edges via warp shuffle, float2 loads.
// Input: output (50,2,100,100,100) fp32. Output: f_u(48,96,96,96) ++ f_v.

#define TOUT 48
#define D 96
#define IN_T 2000000
#define IN_C 1000000
#define IN_Y 10000
#define IN_X 100
#define N_OUT (TOUT * D * D * D)       // 42467328
#define YM 8                           // y outputs per thread
#define NTHREADS (N_OUT / (2 * YM))    // 2654208

__device__ __forceinline__ float2 ldg2(const float* p) {
    return __ldg((const float2*)p);
}
__device__ __forceinline__ float2 shup(float2 v) {
    float2 r;
    r.x = __shfl_up_sync(0xffffffffu, v.x, 1);
    r.y = __shfl_up_sync(0xffffffffu, v.y, 1);
    return r;
}
__device__ __forceinline__ float2 shdn(float2 v) {
    float2 r;
    r.x = __shfl_down_sync(0xffffffffu, v.x, 1);
    r.y = __shfl_down_sync(0xffffffffu, v.y, 1);
    return r;
}

__global__ void __launch_bounds__(256) gs11(
    const float* __restrict__ in, float* __restrict__ out)
{
    int idx = blockIdx.x * 256 + threadIdx.x;
    if (idx >= NTHREADS) return;

    int zp = idx % 48;  int q = idx / 48;
    int x  = q % D;     q /= D;
    int yb = q % (D / YM);
    int t  = q / (D / YM);
    const int y0 = yb * YM;

    const unsigned lane = threadIdx.x & 31u;
    const bool hu = (lane > 0)  && (zp > 0);
    const bool hd = (lane < 31) && (zp < 47);

    // base pointers at (t, ch, y_in = y0, x+2, 2zp+2)
    const float* bu = in + t * IN_T + y0 * IN_Y + (x + 2) * IN_X + (2 * zp + 2);
    const float* bv = bu + IN_C;
    // t+1 centers: y_in = y0+2+k
    const float* nb = bu + IN_T + 2 * IN_Y;

    float* ob = out + ((t * D + y0) * D + x) * D + 2 * zp;

    const float INV_DX2 = 2304.0f / 10000.0f;
    const float C1 = 4.0f / 3.0f;
    const float C2 = -1.0f / 12.0f;
    const float C0 = -7.5f;

    // register rings: center rows y_in = y+0 .. y+4 (out y uses r2 as center)
    float2 ru[5], rv[5];
    #pragma unroll
    for (int k = 0; k < 4; k++) {
        ru[k] = ldg2(bu + k * IN_Y);
        rv[k] = ldg2(bv + k * IN_Y);
    }

    #pragma unroll
    for (int k = 0; k < YM; k++) {
        // new ring row: y_in = y0+k+4
        ru[4] = ldg2(bu + (k + 4) * IN_Y);
        rv[4] = ldg2(bv + (k + 4) * IN_Y);

        const float* xu = bu + (k + 2) * IN_Y;   // center row for x-taps
        const float* xv = bv + (k + 2) * IN_Y;

        // x-taps (4 per channel)
        float2 uxm1 = ldg2(xu - IN_X),     uxp1 = ldg2(xu + IN_X);
        float2 uxm2 = ldg2(xu - 2 * IN_X), uxp2 = ldg2(xu + 2 * IN_X);
        float2 vxm1 = ldg2(xv - IN_X),     vxp1 = ldg2(xv + IN_X);
        float2 vxm2 = ldg2(xv - 2 * IN_X), vxp2 = ldg2(xv + 2 * IN_X);

        // t+1 centers
        float2 un = ldg2(nb + k * IN_Y);
        float2 vn = ldg2(nb + k * IN_Y + IN_C);

        // z-window edges of the center rows via shuffle (boundary fallback)
        float2 cu = ru[2], cv = rv[2];
        float2 uwl = shup(cu), uwr = shdn(cu);
        float2 vwl = shup(cv), vwr = shdn(cv);
        if (!hu) { uwl = ldg2(xu - 2); vwl = ldg2(xv - 2); }
        if (!hd) { uwr = ldg2(xu + 2); vwr = ldg2(xv + 2); }

        // u channel: lane x / lane y of the float2
        float s1ux = uwl.y + cu.y + uxm1.x + uxp1.x + ru[1].x + ru[3].x;
        float s2ux = uwl.x + uwr.x + uxm2.x + uxp2.x + ru[0].x + ru[4].x;
        float s1uy = cu.x + uwr.x + uxm1.y + uxp1.y + ru[1].y + ru[3].y;
        float s2uy = uwl.y + uwr.y + uxm2.y + uxp2.y + ru[0].y + ru[4].y;

        float s1vx = vwl.y + cv.y + vxm1.x + vxp1.x + rv[1].x + rv[3].x;
        float s2vx = vwl.x + vwr.x + vxm2.x + vxp2.x + rv[0].x + rv[4].x;
        float s1vy = cv.x + vwr.x + vxm1.y + vxp1.y + rv[1].y + rv[3].y;
        float s2vy = vwl.y + vwr.y + vxm2.y + vxp2.y + rv[0].y + rv[4].y;

        float lapux = (C0 * cu.x + C1 * s1ux + C2 * s2ux) * INV_DX2;
        float lapuy = (C0 * cu.y + C1 * s1uy + C2 * s2uy) * INV_DX2;
        float lapvx = (C0 * cv.x + C1 * s1vx + C2 * s2vx) * INV_DX2;
        float lapvy = (C0 * cv.y + C1 * s1vy + C2 * s2vy) * INV_DX2;

        float uv2x = cu.x * cv.x * cv.x;
        float uv2y = cu.y * cv.y * cv.y;

        float2 fu, fv;
        fu.x = 0.2f * lapux - uv2x + 0.025f * (1.0f - cu.x) - (un.x - cu.x) * 2.0f;
        fu.y = 0.2f * lapuy - uv2y + 0.025f * (1.0f - cu.y) - (un.y - cu.y) * 2.0f;
        fv.x = 0.1f * lapvx + uv2x - 0.08f * cv.x - (vn.x - cv.x) * 2.0f;
        fv.y = 0.1f * lapvy + uv2y - 0.08f * cv.y - (vn.y - cv.y) * 2.0f;

        *(float2*)(ob + k * (D * D))         = fu;
        *(float2*)(ob + k * (D * D) + N_OUT) = fv;

        // rotate rings (free under full unroll)
        #pragma unroll
        for (int m = 0; m < 4; m++) { ru[m] = ru[m + 1]; rv[m] = rv[m + 1]; }
    }
}

extern "C" void kernel_launch(void* const* d_in, const int* in_sizes, int n_in,
                              void* d_out, int out_size)
{
    const float* in = (const float*)d_in[0];
    float* out = (float*)d_out;
    int blocks = (NTHREADS + 255) / 256;   // 10368
    gs11<<<blocks, 256>>>(in, out);
}

// round 12
// speedup vs baseline: 1.0820x; 1.0820x over previous
#include <cuda_runtime.h>

// Gray-Scott residual: y-march, z-pair/thread, 8 y outputs/thread.
// 5-deep float2 register ring of center rows per channel (y-taps free),
// z-window edges via warp shuffle, float2 loads, single marching pointer.
// R12 = R11 + register diet + __launch_bounds__(256,6).
// Input: output (50,2,100,100,100) fp32. Output: f_u(48,96,96,96) ++ f_v.

#define TOUT 48
#define D 96
#define IN_T 2000000
#define IN_C 1000000
#define IN_Y 10000
#define IN_X 100
#define N_OUT (TOUT * D * D * D)       // 42467328
#define YM 8                           // y outputs per thread
#define NTHREADS (N_OUT / (2 * YM))    // 2654208

__device__ __forceinline__ float2 ldg2(const float* p) {
    return __ldg((const float2*)p);
}
__device__ __forceinline__ float2 shup(float2 v) {
    float2 r;
    r.x = __shfl_up_sync(0xffffffffu, v.x, 1);
    r.y = __shfl_up_sync(0xffffffffu, v.y, 1);
    return r;
}
__device__ __forceinline__ float2 shdn(float2 v) {
    float2 r;
    r.x = __shfl_down_sync(0xffffffffu, v.x, 1);
    r.y = __shfl_down_sync(0xffffffffu, v.y, 1);
    return r;
}

__global__ void __launch_bounds__(256, 6) gs12(
    const float* __restrict__ in, float* __restrict__ out)
{
    int idx = blockIdx.x * 256 + threadIdx.x;
    if (idx >= NTHREADS) return;

    int zp = idx % 48;  int q = idx / 48;
    int x  = q % D;     q /= D;
    int yb = q % (D / YM);
    int t  = q / (D / YM);

    const unsigned lane = threadIdx.x & 31u;
    const bool hu = (lane > 0)  && (zp > 0);
    const bool hd = (lane < 31) && (zp < 47);

    // marching center-row pointer: (t, u, y_in = y0+2, x+2, 2zp+2)
    const float* pc = in + t * IN_T + (yb * YM + 2) * IN_Y
                    + (x + 2) * IN_X + (2 * zp + 2);
    float* ob = out + ((t * D + yb * YM) * D + x) * D + 2 * zp;

    const float INV_DX2 = 2304.0f / 10000.0f;
    const float C1 = 4.0f / 3.0f;
    const float C2 = -1.0f / 12.0f;
    const float C0 = -7.5f;

    // register rings: center rows (ring idx 2 = current center)
    float2 ru[5], rv[5];
    ru[0] = ldg2(pc - 2 * IN_Y); rv[0] = ldg2(pc + IN_C - 2 * IN_Y);
    ru[1] = ldg2(pc - IN_Y);     rv[1] = ldg2(pc + IN_C - IN_Y);
    ru[2] = ldg2(pc);            rv[2] = ldg2(pc + IN_C);
    ru[3] = ldg2(pc + IN_Y);     rv[3] = ldg2(pc + IN_C + IN_Y);

    #pragma unroll
    for (int k = 0; k < YM; k++) {
        // ring refill (row y_in = y+4, prefetch distance 2 iters)
        ru[4] = ldg2(pc + 2 * IN_Y);
        rv[4] = ldg2(pc + IN_C + 2 * IN_Y);

        // x-taps (center row)
        float2 uxm1 = ldg2(pc - IN_X),            uxp1 = ldg2(pc + IN_X);
        float2 uxm2 = ldg2(pc - 2 * IN_X),        uxp2 = ldg2(pc + 2 * IN_X);
        float2 vxm1 = ldg2(pc + IN_C - IN_X),     vxp1 = ldg2(pc + IN_C + IN_X);
        float2 vxm2 = ldg2(pc + IN_C - 2 * IN_X), vxp2 = ldg2(pc + IN_C + 2 * IN_X);

        // t+1 centers (same spatial spot, next time slice)
        float2 un = ldg2(pc + IN_T);
        float2 vn = ldg2(pc + IN_T + IN_C);

        // z-window edges via shuffle (boundary fallback)
        float2 cu = ru[2], cv = rv[2];
        float2 uwl = shup(cu), uwr = shdn(cu);
        float2 vwl = shup(cv), vwr = shdn(cv);
        if (!hu) { uwl = ldg2(pc - 2); vwl = ldg2(pc + IN_C - 2); }
        if (!hd) { uwr = ldg2(pc + 2); vwr = ldg2(pc + IN_C + 2); }

        float s1ux = uwl.y + cu.y + uxm1.x + uxp1.x + ru[1].x + ru[3].x;
        float s2ux = uwl.x + uwr.x + uxm2.x + uxp2.x + ru[0].x + ru[4].x;
        float s1uy = cu.x + uwr.x + uxm1.y + uxp1.y + ru[1].y + ru[3].y;
        float s2uy = uwl.y + uwr.y + uxm2.y + uxp2.y + ru[0].y + ru[4].y;

        float s1vx = vwl.y + cv.y + vxm1.x + vxp1.x + rv[1].x + rv[3].x;
        float s2vx = vwl.x + vwr.x + vxm2.x + vxp2.x + rv[0].x + rv[4].x;
        float s1vy = cv.x + vwr.x + vxm1.y + vxp1.y + rv[1].y + rv[3].y;
        float s2vy = vwl.y + vwr.y + vxm2.y + vxp2.y + rv[0].y + rv[4].y;

        float lapux = (C0 * cu.x + C1 * s1ux + C2 * s2ux) * INV_DX2;
        float lapuy = (C0 * cu.y + C1 * s1uy + C2 * s2uy) * INV_DX2;
        float lapvx = (C0 * cv.x + C1 * s1vx + C2 * s2vx) * INV_DX2;
        float lapvy = (C0 * cv.y + C1 * s1vy + C2 * s2vy) * INV_DX2;

        float uv2x = cu.x * cv.x * cv.x;
        float uv2y = cu.y * cv.y * cv.y;

        float2 fu, fv;
        fu.x = 0.2f * lapux - uv2x + 0.025f * (1.0f - cu.x) - (un.x - cu.x) * 2.0f;
        fu.y = 0.2f * lapuy - uv2y + 0.025f * (1.0f - cu.y) - (un.y - cu.y) * 2.0f;
        fv.x = 0.1f * lapvx + uv2x - 0.08f * cv.x - (vn.x - cv.x) * 2.0f;
        fv.y = 0.1f * lapvy + uv2y - 0.08f * cv.y - (vn.y - cv.y) * 2.0f;

        *(float2*)ob           = fu;
        *(float2*)(ob + N_OUT) = fv;

        // rotate rings, advance pointers
        #pragma unroll
        for (int m = 0; m < 4; m++) { ru[m] = ru[m + 1]; rv[m] = rv[m + 1]; }
        pc += IN_Y;
        ob += D * D;
    }
}

extern "C" void kernel_launch(void* const* d_in, const int* in_sizes, int n_in,
                              void* d_out, int out_size)
{
    const float* in = (const float*)d_in[0];
    float* out = (float*)d_out;
    int blocks = (NTHREADS + 255) / 256;   // 10368
    gs12<<<blocks, 256>>>(in, out);
}